// round 1
// baseline (speedup 1.0000x reference)
#include <cuda_runtime.h>
#include <cstdint>
#include <cstddef>

// ---------------- problem constants ----------------
#define TOKS 4096            // B*S
#define DMODEL 512
#define NEXP 16
#define DHID 2048            // 4*D
#define DSH  1024            // 2*D
#define INV_TEMP (1.0f/0.7f)
#define LN_EPS 1e-5f
#define SHARED_SCALE 0.25f

// ---------------- GEMM tiling ----------------
#define BM 128
#define BN 128
#define BKK 16
#define MAX_TILES 80                 // sum_e ceil(n_e/128) <= 8192/128 + 16 = 80
#define PADMAX (MAX_TILES*BM)        // 10240 padded assignment rows

// ---------------- device scratch (static: allocation-free) ----------------
__device__ float g_h[TOKS*DMODEL];
__device__ float g_mix[TOKS*DMODEL];
__device__ float g_fh[TOKS*DMODEL];
__device__ float g_sact[TOKS*DSH];
__device__ float g_ffact[(size_t)TOKS*DHID];
__device__ float g_act1[(size_t)PADMAX*DHID];
__device__ float g_y[(size_t)PADMAX*DMODEL];
__device__ int   g_cnt[NEXP];
__device__ int   g_fill[NEXP];
__device__ int   g_off[NEXP];
__device__ int   g_tile_e[MAX_TILES];
__device__ int   g_perm_tok[PADMAX];
__device__ float g_perm_w[PADMAX];
__device__ int   g_top_i[TOKS*2];
__device__ float g_top_w[TOKS*2];
__device__ int   g_apos[TOKS*2];

__device__ __forceinline__ float silu(float v) {
    return v * (1.0f / (1.0f + __expf(-v)));
}

// ---------------- small kernels ----------------
__global__ void zero_cnt_kernel() {
    if (threadIdx.x < NEXP) g_cnt[threadIdx.x] = 0;
}

// LayerNorm over D=512; optionally fused router (logits + softmax + top-2).
template<bool ROUTER>
__global__ void __launch_bounds__(128) ln_kernel(
    const float* __restrict__ x,
    const float* __restrict__ gamma, const float* __restrict__ beta,
    const float* __restrict__ rw, const float* __restrict__ rb,
    float* __restrict__ out)
{
    int tok = blockIdx.x, tid = threadIdx.x;
    __shared__ float hs[DMODEL];
    __shared__ float red[2][4];
    __shared__ float logits[NEXP];

    float4 v = *(const float4*)&x[(size_t)tok*DMODEL + tid*4];
    float s = v.x+v.y+v.z+v.w;
    float q = v.x*v.x+v.y*v.y+v.z*v.z+v.w*v.w;
    #pragma unroll
    for (int o = 16; o; o >>= 1) {
        s += __shfl_xor_sync(0xffffffffu, s, o);
        q += __shfl_xor_sync(0xffffffffu, q, o);
    }
    if ((tid & 31) == 0) { red[0][tid>>5] = s; red[1][tid>>5] = q; }
    __syncthreads();
    s = red[0][0]+red[0][1]+red[0][2]+red[0][3];
    q = red[1][0]+red[1][1]+red[1][2]+red[1][3];
    float mu  = s * (1.0f/DMODEL);
    float var = q * (1.0f/DMODEL) - mu*mu;
    float rs  = rsqrtf(var + LN_EPS);

    int d = tid*4;
    float4 o;
    o.x = (v.x-mu)*rs*gamma[d+0] + beta[d+0];
    o.y = (v.y-mu)*rs*gamma[d+1] + beta[d+1];
    o.z = (v.z-mu)*rs*gamma[d+2] + beta[d+2];
    o.w = (v.w-mu)*rs*gamma[d+3] + beta[d+3];
    *(float4*)&out[(size_t)tok*DMODEL + d] = o;

    if (ROUTER) {
        *(float4*)&hs[d] = o;
        __syncthreads();
        if (tid < NEXP) {
            float acc = 0.0f;
            #pragma unroll 8
            for (int dd = 0; dd < DMODEL; dd++) acc += hs[dd] * rw[dd*NEXP + tid];
            logits[tid] = (acc + rb[tid]) * INV_TEMP;
        }
        __syncthreads();
        if (tid == 0) {
            float m = logits[0];
            #pragma unroll
            for (int e = 1; e < NEXP; e++) m = fmaxf(m, logits[e]);
            float p[NEXP]; float sum = 0.0f;
            #pragma unroll
            for (int e = 0; e < NEXP; e++) { p[e] = __expf(logits[e]-m); sum += p[e]; }
            float inv = 1.0f / sum;
            int i0 = 0; float b0 = p[0];
            #pragma unroll
            for (int e = 1; e < NEXP; e++) if (p[e] > b0) { b0 = p[e]; i0 = e; }
            int i1 = -1; float b1 = -1.0f;
            #pragma unroll
            for (int e = 0; e < NEXP; e++) if (e != i0 && p[e] > b1) { b1 = p[e]; i1 = e; }
            g_top_i[tok*2+0] = i0; g_top_i[tok*2+1] = i1;
            g_top_w[tok*2+0] = b0*inv; g_top_w[tok*2+1] = b1*inv;
            atomicAdd(&g_cnt[i0], 1);
            atomicAdd(&g_cnt[i1], 1);
        }
    }
}

// Build padded per-expert offsets + tile->expert map; reset fill counters.
__global__ void setup_kernel() {
    int tid = threadIdx.x;
    for (int i = tid; i < PADMAX; i += blockDim.x) g_perm_tok[i] = -1;
    if (tid < MAX_TILES) g_tile_e[tid] = -1;
    if (tid < NEXP) g_fill[tid] = 0;
    __syncthreads();
    if (tid == 0) {
        int running = 0;
        for (int e = 0; e < NEXP; e++) {
            g_off[e] = running;
            int nt = (g_cnt[e] + BM - 1) / BM;
            int t0 = running / BM;
            for (int t = 0; t < nt; t++) g_tile_e[t0 + t] = e;
            running += nt * BM;
        }
    }
}

__global__ void scatter_kernel() {
    int tok = blockIdx.x * blockDim.x + threadIdx.x;
    if (tok >= TOKS) return;
    #pragma unroll
    for (int k = 0; k < 2; k++) {
        int e = g_top_i[tok*2+k];
        int pos = atomicAdd(&g_fill[e], 1);
        int gp = g_off[e] + pos;
        g_perm_tok[gp] = tok;
        g_perm_w[gp]   = g_top_w[tok*2+k];
        g_apos[tok*2+k] = gp;
    }
}

// mix[tok] += w0*y[g0] + w1*y[g1]  (deterministic fixed-order combine)
__global__ void __launch_bounds__(128) combine_kernel() {
    int tok = blockIdx.x, tid = threadIdx.x;
    int d = tid*4;
    int g0 = g_apos[tok*2+0], g1 = g_apos[tok*2+1];
    float w0 = g_top_w[tok*2+0], w1 = g_top_w[tok*2+1];
    float4 m = *(float4*)&g_mix[(size_t)tok*DMODEL + d];
    float4 a = *(const float4*)&g_y[(size_t)g0*DMODEL + d];
    float4 b = *(const float4*)&g_y[(size_t)g1*DMODEL + d];
    m.x += w0*a.x + w1*b.x;
    m.y += w0*a.y + w1*b.y;
    m.z += w0*a.z + w1*b.z;
    m.w += w0*a.w + w1*b.w;
    *(float4*)&g_mix[(size_t)tok*DMODEL + d] = m;
}

// ---------------- generic SGEMM: C(MxN) = epi(A(MxK) @ B(KxN) + bias) ----------------
// EPI: 0 = silu, 1 = *scale store, 2 = plain store, 3 = + r1 + r2 (final residual)
// GATHER: A rows gathered through g_perm_tok (padding rows -> zero)
// EXPERT: B/bias offset per tile via g_tile_e
template<int EPI, bool GATHER, bool EXPERT>
__global__ void __launch_bounds__(256, 2) gemm_kernel(
    const float* __restrict__ A, const float* __restrict__ B,
    const float* __restrict__ bias, float* __restrict__ C,
    int K, int N,
    const float* __restrict__ r1, const float* __restrict__ r2, float scale)
{
    __shared__ float As[BKK][BM];
    __shared__ float Bs[BKK][BN];

    int tid = threadIdx.x;
    int row0 = blockIdx.x * BM;
    int col0 = blockIdx.y * BN;

    const float* Bp = B;
    const float* bp = bias;
    if (EXPERT) {
        int e = g_tile_e[blockIdx.x];
        if (e < 0) return;
        Bp = B + (size_t)e * K * N;
        bp = bias + (size_t)e * N;
    }

    // A-load assignment: 512 float4 items; thread handles items tid, tid+256
    int ra = tid >> 2, qa = tid & 3;          // row within tile, k-quad
    const float* Arow0; const float* Arow1;
    if (GATHER) {
        int t0 = g_perm_tok[row0 + ra];
        int t1 = g_perm_tok[row0 + ra + 64];
        Arow0 = (t0 >= 0) ? A + (size_t)t0 * K : nullptr;
        Arow1 = (t1 >= 0) ? A + (size_t)t1 * K : nullptr;
    } else {
        Arow0 = A + (size_t)(row0 + ra) * K;
        Arow1 = A + (size_t)(row0 + ra + 64) * K;
    }
    // B-load assignment
    int kb = tid >> 5, qb = tid & 31;

    int ty = tid >> 4, tx = tid & 15;
    float acc[8][8];
    #pragma unroll
    for (int i = 0; i < 8; i++)
        #pragma unroll
        for (int j = 0; j < 8; j++) acc[i][j] = 0.0f;

    const float4 z4 = make_float4(0.f, 0.f, 0.f, 0.f);

    for (int k0 = 0; k0 < K; k0 += BKK) {
        float4 va0 = (!GATHER || Arow0) ? *(const float4*)&Arow0[k0 + qa*4] : z4;
        float4 va1 = (!GATHER || Arow1) ? *(const float4*)&Arow1[k0 + qa*4] : z4;
        As[qa*4+0][ra]    = va0.x; As[qa*4+1][ra]    = va0.y;
        As[qa*4+2][ra]    = va0.z; As[qa*4+3][ra]    = va0.w;
        As[qa*4+0][ra+64] = va1.x; As[qa*4+1][ra+64] = va1.y;
        As[qa*4+2][ra+64] = va1.z; As[qa*4+3][ra+64] = va1.w;

        float4 vb0 = *(const float4*)&Bp[(size_t)(k0+kb)  *N + col0 + qb*4];
        float4 vb1 = *(const float4*)&Bp[(size_t)(k0+kb+8)*N + col0 + qb*4];
        *(float4*)&Bs[kb  ][qb*4] = vb0;
        *(float4*)&Bs[kb+8][qb*4] = vb1;
        __syncthreads();

        #pragma unroll
        for (int k = 0; k < BKK; k++) {
            float4 a0 = *(const float4*)&As[k][ty*8];
            float4 a1 = *(const float4*)&As[k][ty*8+4];
            float4 b0 = *(const float4*)&Bs[k][tx*8];
            float4 b1 = *(const float4*)&Bs[k][tx*8+4];
            float av[8] = {a0.x,a0.y,a0.z,a0.w,a1.x,a1.y,a1.z,a1.w};
            float bv[8] = {b0.x,b0.y,b0.z,b0.w,b1.x,b1.y,b1.z,b1.w};
            #pragma unroll
            for (int i = 0; i < 8; i++)
                #pragma unroll
                for (int j = 0; j < 8; j++)
                    acc[i][j] += av[i] * bv[j];
        }
        __syncthreads();
    }

    // epilogue: each thread owns rows row0+ty*8+i, cols col0+tx*8..+7
    #pragma unroll
    for (int i = 0; i < 8; i++) {
        int m = row0 + ty*8 + i;
        size_t base = (size_t)m * N + col0 + tx*8;
        float vs[8];
        #pragma unroll
        for (int j = 0; j < 8; j++) {
            float v = acc[i][j] + bp[col0 + tx*8 + j];
            if (EPI == 0) v = silu(v);
            else if (EPI == 1) v = v * scale;
            else if (EPI == 3) v = v + r1[base + j] + r2[base + j];
            vs[j] = v;
        }
        *(float4*)&C[base]     = make_float4(vs[0], vs[1], vs[2], vs[3]);
        *(float4*)&C[base + 4] = make_float4(vs[4], vs[5], vs[6], vs[7]);
    }
}

// ---------------- launcher ----------------
extern "C" void kernel_launch(void* const* d_in, const int* in_sizes, int n_in,
                              void* d_out, int out_size)
{
    const float* x      = (const float*)d_in[0];
    const float* ln_g   = (const float*)d_in[1];
    const float* ln_b   = (const float*)d_in[2];
    const float* rw     = (const float*)d_in[3];
    const float* rb     = (const float*)d_in[4];
    const float* ew1    = (const float*)d_in[5];
    const float* eb1    = (const float*)d_in[6];
    const float* ew2    = (const float*)d_in[7];
    const float* eb2    = (const float*)d_in[8];
    const float* sw1    = (const float*)d_in[9];
    const float* sb1    = (const float*)d_in[10];
    const float* sw2    = (const float*)d_in[11];
    const float* sb2    = (const float*)d_in[12];
    const float* ffln_g = (const float*)d_in[13];
    const float* ffln_b = (const float*)d_in[14];
    const float* ffw1   = (const float*)d_in[15];
    const float* ffb1   = (const float*)d_in[16];
    const float* ffw2   = (const float*)d_in[17];
    const float* ffb2   = (const float*)d_in[18];
    float* out = (float*)d_out;

    void* p;
    cudaGetSymbolAddress(&p, g_h);     float* ph     = (float*)p;
    cudaGetSymbolAddress(&p, g_mix);   float* pmix   = (float*)p;
    cudaGetSymbolAddress(&p, g_fh);    float* pfh    = (float*)p;
    cudaGetSymbolAddress(&p, g_sact);  float* psact  = (float*)p;
    cudaGetSymbolAddress(&p, g_ffact); float* pffact = (float*)p;
    cudaGetSymbolAddress(&p, g_act1);  float* pact1  = (float*)p;
    cudaGetSymbolAddress(&p, g_y);     float* py     = (float*)p;

    // 1. reset expert counts
    zero_cnt_kernel<<<1, 32>>>();
    // 2. input LN + router + top-2
    ln_kernel<true><<<TOKS, 128>>>(x, ln_g, ln_b, rw, rb, ph);
    // 3. padded offsets + tile map
    setup_kernel<<<1, 256>>>();
    // 4. scatter assignments into permuted order
    scatter_kernel<<<TOKS/256, 256>>>();
    // 5. expert GEMM1 + SiLU (gathered rows): act1 = silu(h[perm] @ ew1[e] + eb1[e])
    gemm_kernel<0, true,  true ><<<dim3(MAX_TILES, DHID/BN), 256>>>(
        ph, ew1, eb1, pact1, DMODEL, DHID, nullptr, nullptr, 1.0f);
    // 6. expert GEMM2: y = act1 @ ew2[e] + eb2[e]
    gemm_kernel<2, false, true ><<<dim3(MAX_TILES, DMODEL/BN), 256>>>(
        pact1, ew2, eb2, py, DHID, DMODEL, nullptr, nullptr, 1.0f);
    // 7. shared expert GEMM1 + SiLU
    gemm_kernel<0, false, false><<<dim3(TOKS/BM, DSH/BN), 256>>>(
        ph, sw1, sb1, psact, DMODEL, DSH, nullptr, nullptr, 1.0f);
    // 8. shared expert GEMM2 * 0.25 -> mix
    gemm_kernel<1, false, false><<<dim3(TOKS/BM, DMODEL/BN), 256>>>(
        psact, sw2, sb2, pmix, DSH, DMODEL, nullptr, nullptr, SHARED_SCALE);
    // 9. add top-2 weighted expert outputs -> mix = moe_out
    combine_kernel<<<TOKS, 128>>>();
    // 10. final-FF LayerNorm
    ln_kernel<false><<<TOKS, 128>>>(pmix, ffln_g, ffln_b, nullptr, nullptr, pfh);
    // 11. FF GEMM1 + SiLU
    gemm_kernel<0, false, false><<<dim3(TOKS/BM, DHID/BN), 256>>>(
        pfh, ffw1, ffb1, pffact, DMODEL, DHID, nullptr, nullptr, 1.0f);
    // 12. FF GEMM2 + x + moe_out -> out
    gemm_kernel<3, false, false><<<dim3(TOKS/BM, DMODEL/BN), 256>>>(
        pffact, ffw2, ffb2, out, DHID, DMODEL, x, pmix, 1.0f);
}

// round 3
// speedup vs baseline: 3.3359x; 3.3359x over previous
#include <cuda_runtime.h>
#include <cstdint>
#include <cstddef>

// ---------------- problem constants ----------------
#define TOKS 4096
#define DMODEL 512
#define NEXP 16
#define DHID 2048
#define DSH  1024
#define INV_TEMP (1.0f/0.7f)
#define LN_EPS 1e-5f
#define SHARED_SCALE 0.25f

#define BM 128
#define BN 128
#define BK 32
#define MAX_TILES 80
#define PADMAX (MAX_TILES*BM)

#define STAGE_BYTES 32768           // A 16KB + B 16KB
#define SMEM_TOTAL (2*STAGE_BYTES)  // double buffer

// ---------------- device scratch ----------------
__device__ float g_h[TOKS*DMODEL];
__device__ float g_mix[TOKS*DMODEL];
__device__ float g_fh[TOKS*DMODEL];
__device__ float g_sact[TOKS*DSH];
__device__ float g_ffact[(size_t)TOKS*DHID];
__device__ float g_act1[(size_t)PADMAX*DHID];
__device__ float g_y[(size_t)PADMAX*DMODEL];
__device__ int   g_cnt[NEXP];
__device__ int   g_fill[NEXP];
__device__ int   g_off[NEXP];
__device__ int   g_tile_e[MAX_TILES];
__device__ int   g_perm_tok[PADMAX];
__device__ int   g_top_i[TOKS*2];
__device__ float g_top_w[TOKS*2];
__device__ int   g_apos[TOKS*2];
// transposed (+tf32-rounded) weights [N][K]
__device__ float g_ew1T[(size_t)NEXP*DHID*DMODEL];
__device__ float g_ew2T[(size_t)NEXP*DMODEL*DHID];
__device__ float g_sw1T[(size_t)DSH*DMODEL];
__device__ float g_sw2T[(size_t)DMODEL*DSH];
__device__ float g_ffw1T[(size_t)DHID*DMODEL];
__device__ float g_ffw2T[(size_t)DMODEL*DHID];

__device__ __forceinline__ float silu(float v) {
    return v * (1.0f / (1.0f + __expf(-v)));
}
__device__ __forceinline__ float tf32r(float v) {
    uint32_t o;
    asm("cvt.rna.tf32.f32 %0, %1;" : "=r"(o) : "f"(v));
    return __uint_as_float(o);
}
__device__ __forceinline__ uint32_t smem_u32(const void* p) {
    uint32_t a;
    asm("{ .reg .u64 t; cvta.to.shared.u64 t, %1; cvt.u32.u64 %0, t; }" : "=r"(a) : "l"(p));
    return a;
}
__device__ __forceinline__ void cp16(uint32_t dst, const void* src, int sz) {
    asm volatile("cp.async.cg.shared.global [%0], [%1], 16, %2;"
        :: "r"(dst), "l"(src), "r"(sz) : "memory");
}
#define CP_COMMIT() asm volatile("cp.async.commit_group;" ::: "memory")
#define CP_WAIT1()  asm volatile("cp.async.wait_group 1;" ::: "memory")
#define LDSM_X4(r0,r1,r2,r3,addr) \
    asm volatile("ldmatrix.sync.aligned.m8n8.x4.shared.b16 {%0,%1,%2,%3}, [%4];" \
        : "=r"(r0),"=r"(r1),"=r"(r2),"=r"(r3) : "r"(addr))

__device__ __forceinline__ void mma_tf32(float* c, const uint32_t* a, const uint32_t* b) {
    asm volatile(
        "mma.sync.aligned.m16n8k8.row.col.f32.tf32.tf32.f32 "
        "{%0,%1,%2,%3}, {%4,%5,%6,%7}, {%8,%9}, {%0,%1,%2,%3};"
        : "+f"(c[0]), "+f"(c[1]), "+f"(c[2]), "+f"(c[3])
        : "r"(a[0]), "r"(a[1]), "r"(a[2]), "r"(a[3]), "r"(b[0]), "r"(b[1]));
}

// ---------------- small kernels ----------------
__global__ void zero_cnt_kernel() {
    if (threadIdx.x < NEXP) g_cnt[threadIdx.x] = 0;
}

template<bool ROUTER>
__global__ void __launch_bounds__(128) ln_kernel(
    const float* __restrict__ x,
    const float* __restrict__ gamma, const float* __restrict__ beta,
    const float* __restrict__ rw, const float* __restrict__ rb,
    float* __restrict__ out)
{
    int tok = blockIdx.x, tid = threadIdx.x;
    __shared__ float hs[DMODEL];
    __shared__ float red[2][4];
    __shared__ float logits[NEXP];

    float4 v = *(const float4*)&x[(size_t)tok*DMODEL + tid*4];
    float s = v.x+v.y+v.z+v.w;
    float q = v.x*v.x+v.y*v.y+v.z*v.z+v.w*v.w;
    #pragma unroll
    for (int o = 16; o; o >>= 1) {
        s += __shfl_xor_sync(0xffffffffu, s, o);
        q += __shfl_xor_sync(0xffffffffu, q, o);
    }
    if ((tid & 31) == 0) { red[0][tid>>5] = s; red[1][tid>>5] = q; }
    __syncthreads();
    s = red[0][0]+red[0][1]+red[0][2]+red[0][3];
    q = red[1][0]+red[1][1]+red[1][2]+red[1][3];
    float mu  = s * (1.0f/DMODEL);
    float var = q * (1.0f/DMODEL) - mu*mu;
    float rs  = rsqrtf(var + LN_EPS);

    int d = tid*4;
    float4 o;
    o.x = tf32r((v.x-mu)*rs*gamma[d+0] + beta[d+0]);
    o.y = tf32r((v.y-mu)*rs*gamma[d+1] + beta[d+1]);
    o.z = tf32r((v.z-mu)*rs*gamma[d+2] + beta[d+2]);
    o.w = tf32r((v.w-mu)*rs*gamma[d+3] + beta[d+3]);
    *(float4*)&out[(size_t)tok*DMODEL + d] = o;

    if (ROUTER) {
        *(float4*)&hs[d] = o;
        __syncthreads();
        if (tid < NEXP) {
            float acc = 0.0f;
            #pragma unroll 8
            for (int dd = 0; dd < DMODEL; dd++) acc += hs[dd] * rw[dd*NEXP + tid];
            logits[tid] = (acc + rb[tid]) * INV_TEMP;
        }
        __syncthreads();
        if (tid == 0) {
            float m = logits[0];
            #pragma unroll
            for (int e = 1; e < NEXP; e++) m = fmaxf(m, logits[e]);
            float p[NEXP]; float sum = 0.0f;
            #pragma unroll
            for (int e = 0; e < NEXP; e++) { p[e] = __expf(logits[e]-m); sum += p[e]; }
            float inv = 1.0f / sum;
            int i0 = 0; float b0 = p[0];
            #pragma unroll
            for (int e = 1; e < NEXP; e++) if (p[e] > b0) { b0 = p[e]; i0 = e; }
            int i1 = -1; float b1 = -1.0f;
            #pragma unroll
            for (int e = 0; e < NEXP; e++) if (e != i0 && p[e] > b1) { b1 = p[e]; i1 = e; }
            g_top_i[tok*2+0] = i0; g_top_i[tok*2+1] = i1;
            g_top_w[tok*2+0] = b0*inv; g_top_w[tok*2+1] = b1*inv;
            atomicAdd(&g_cnt[i0], 1);
            atomicAdd(&g_cnt[i1], 1);
        }
    }
}

__global__ void setup_kernel() {
    int tid = threadIdx.x;
    for (int i = tid; i < PADMAX; i += blockDim.x) g_perm_tok[i] = -1;
    if (tid < MAX_TILES) g_tile_e[tid] = -1;
    if (tid < NEXP) g_fill[tid] = 0;
    __syncthreads();
    if (tid == 0) {
        int running = 0;
        for (int e = 0; e < NEXP; e++) {
            g_off[e] = running;
            int nt = (g_cnt[e] + BM - 1) / BM;
            int t0 = running / BM;
            for (int t = 0; t < nt; t++) g_tile_e[t0 + t] = e;
            running += nt * BM;
        }
    }
}

__global__ void scatter_kernel() {
    int tok = blockIdx.x * blockDim.x + threadIdx.x;
    if (tok >= TOKS) return;
    #pragma unroll
    for (int k = 0; k < 2; k++) {
        int e = g_top_i[tok*2+k];
        int pos = atomicAdd(&g_fill[e], 1);
        int gp = g_off[e] + pos;
        g_perm_tok[gp] = tok;
        g_apos[tok*2+k] = gp;
    }
}

__global__ void __launch_bounds__(128) combine_kernel() {
    int tok = blockIdx.x, tid = threadIdx.x;
    int d = tid*4;
    int g0 = g_apos[tok*2+0], g1 = g_apos[tok*2+1];
    float w0 = g_top_w[tok*2+0], w1 = g_top_w[tok*2+1];
    float4 m = *(float4*)&g_mix[(size_t)tok*DMODEL + d];
    float4 a = *(const float4*)&g_y[(size_t)g0*DMODEL + d];
    float4 b = *(const float4*)&g_y[(size_t)g1*DMODEL + d];
    m.x += w0*a.x + w1*b.x;
    m.y += w0*a.y + w1*b.y;
    m.z += w0*a.z + w1*b.z;
    m.w += w0*a.w + w1*b.w;
    *(float4*)&g_mix[(size_t)tok*DMODEL + d] = m;
}

// [K][N] -> [N][K] tiled transpose + tf32 rounding (per blockIdx.z matrix)
__global__ void __launch_bounds__(256) transpose_kernel(
    const float* __restrict__ in, float* __restrict__ out, int K, int N)
{
    __shared__ float t[32][33];
    size_t off = (size_t)blockIdx.z * (size_t)K * (size_t)N;
    const float* ip = in + off;
    float* op = out + off;
    int n0 = blockIdx.x * 32, k0 = blockIdx.y * 32;
    #pragma unroll
    for (int i = 0; i < 32; i += 8)
        t[threadIdx.y + i][threadIdx.x] =
            tf32r(ip[(size_t)(k0 + threadIdx.y + i) * N + n0 + threadIdx.x]);
    __syncthreads();
    #pragma unroll
    for (int i = 0; i < 32; i += 8)
        op[(size_t)(n0 + threadIdx.y + i) * K + k0 + threadIdx.x] = t[threadIdx.x][threadIdx.y + i];
}

// ---------------- tf32 mma.sync GEMM ----------------
// C[128x128] = epi(A[M,K] @ BT[N,K]^T + bias)
// EPI: 0=silu(+tf32 round), 1=*scale, 2=store, 3=+r1+r2
template<int EPI, bool GATHER, bool EXPERT>
__global__ void __launch_bounds__(256) mm_gemm(
    const float* __restrict__ A, const float* __restrict__ BT,
    const float* __restrict__ bias, float* __restrict__ C,
    int K, int N,
    const float* __restrict__ r1, const float* __restrict__ r2, float scale)
{
    extern __shared__ char smem[];
    const uint32_t sbase = smem_u32(smem);
    const int tid = threadIdx.x;
    const int wid = tid >> 5, lid = tid & 31;
    const int row0 = blockIdx.x * BM;
    const int col0 = blockIdx.y * BN;

    const float* Bp = BT;
    const float* bp = bias;
    if (EXPERT) {
        int e = g_tile_e[blockIdx.x];
        if (e < 0) return;
        Bp = BT + (size_t)e * (size_t)K * N;
        bp = bias + (size_t)e * N;
    }

    // ---- per-thread cp.async slots (4 A chunks + 4 B chunks of 16B) ----
    const float* asrc[4]; int asz[4]; uint32_t adst[4];
    const float* bsrc[4]; uint32_t bdst[4];
    #pragma unroll
    for (int i = 0; i < 4; i++) {
        int id = tid + i * 256;
        int row = id >> 3, c = id & 7;
        uint32_t sw = (uint32_t)(row * 128 + ((c ^ (row & 7)) << 4));
        if (GATHER) {
            int t = g_perm_tok[row0 + row];
            asrc[i] = (t >= 0) ? (A + (size_t)t * K + c * 4) : A;
            asz[i]  = (t >= 0) ? 16 : 0;
        } else {
            asrc[i] = A + (size_t)(row0 + row) * K + c * 4;
            asz[i]  = 16;
        }
        adst[i] = sw;
        bsrc[i] = Bp + (size_t)(col0 + row) * K + c * 4;
        bdst[i] = 16384u + sw;
    }

    // ---- fragment address precompute ----
    const int wm = wid & 1;         // m half (64 rows)
    const int wn = wid >> 1;        // n quarter (32 cols)
    const uint32_t xorv = (uint32_t)(lid & 7);
    const uint32_t acb = (uint32_t)((lid >> 4) & 1);   // A chunk low/high bit
    const uint32_t bcb = (uint32_t)((lid >> 3) & 1);   // B chunk bit
    uint32_t abase[4];
    #pragma unroll
    for (int mt = 0; mt < 4; mt++) {
        int arow = wm*64 + mt*16 + (lid & 7) + ((lid >> 3) & 1) * 8;
        abase[mt] = (uint32_t)(arow * 128);
    }
    uint32_t bbase[2];
    #pragma unroll
    for (int p = 0; p < 2; p++) {
        int brow = wn*32 + p*16 + ((lid >> 4) & 1) * 8 + (lid & 7);
        bbase[p] = 16384u + (uint32_t)(brow * 128);
    }

    float acc[4][4][4];
    #pragma unroll
    for (int mt = 0; mt < 4; mt++)
        #pragma unroll
        for (int nt = 0; nt < 4; nt++)
            #pragma unroll
            for (int u = 0; u < 4; u++) acc[mt][nt][u] = 0.0f;

    const int nst = K / BK;

    // prologue: stages 0,1
    #pragma unroll
    for (int s = 0; s < 2; s++) {
        uint32_t sb = sbase + s * STAGE_BYTES;
        #pragma unroll
        for (int i = 0; i < 4; i++) cp16(sb + adst[i], asrc[i] + s*BK, asz[i]);
        #pragma unroll
        for (int i = 0; i < 4; i++) cp16(sb + bdst[i], bsrc[i] + s*BK, 16);
        CP_COMMIT();
    }

    for (int c = 0; c < nst; c++) {
        CP_WAIT1();
        __syncthreads();
        uint32_t sb = sbase + (c & 1) * STAGE_BYTES;

        #pragma unroll
        for (int kc = 0; kc < 4; kc++) {
            uint32_t af[4][4];
            #pragma unroll
            for (int mt = 0; mt < 4; mt++) {
                uint32_t addr = sb + abase[mt] + (((((uint32_t)kc << 1) | acb) ^ xorv) << 4);
                LDSM_X4(af[mt][0], af[mt][1], af[mt][2], af[mt][3], addr);
            }
            uint32_t bf[2][4];
            #pragma unroll
            for (int p = 0; p < 2; p++) {
                uint32_t addr = sb + bbase[p] + (((((uint32_t)kc << 1) | bcb) ^ xorv) << 4);
                LDSM_X4(bf[p][0], bf[p][1], bf[p][2], bf[p][3], addr);
            }
            #pragma unroll
            for (int mt = 0; mt < 4; mt++)
                #pragma unroll
                for (int nt = 0; nt < 4; nt++)
                    mma_tf32(acc[mt][nt], af[mt], &bf[nt >> 1][(nt & 1) * 2]);
        }
        __syncthreads();

        int nx = c + 2;
        if (nx < nst) {
            uint32_t sb2 = sbase + (nx & 1) * STAGE_BYTES;
            #pragma unroll
            for (int i = 0; i < 4; i++) cp16(sb2 + adst[i], asrc[i] + nx*BK, asz[i]);
            #pragma unroll
            for (int i = 0; i < 4; i++) cp16(sb2 + bdst[i], bsrc[i] + nx*BK, 16);
        }
        CP_COMMIT();
    }

    // ---- epilogue ----
    const int g = lid >> 2, t = lid & 3;
    #pragma unroll
    for (int mt = 0; mt < 4; mt++) {
        int rA = row0 + wm*64 + mt*16 + g;
        #pragma unroll
        for (int nt = 0; nt < 4; nt++) {
            int cb = col0 + wn*32 + nt*8 + t*2;
            float bb0 = bp[cb], bb1 = bp[cb + 1];
            float v0 = acc[mt][nt][0] + bb0;
            float v1 = acc[mt][nt][1] + bb1;
            float v2 = acc[mt][nt][2] + bb0;
            float v3 = acc[mt][nt][3] + bb1;
            size_t p0 = (size_t)rA * N + cb;
            size_t p1 = (size_t)(rA + 8) * N + cb;
            if (EPI == 0) {
                v0 = tf32r(silu(v0)); v1 = tf32r(silu(v1));
                v2 = tf32r(silu(v2)); v3 = tf32r(silu(v3));
            } else if (EPI == 1) {
                v0 *= scale; v1 *= scale; v2 *= scale; v3 *= scale;
            } else if (EPI == 3) {
                v0 += r1[p0]   + r2[p0];
                v1 += r1[p0+1] + r2[p0+1];
                v2 += r1[p1]   + r2[p1];
                v3 += r1[p1+1] + r2[p1+1];
            }
            *(float2*)&C[p0] = make_float2(v0, v1);
            *(float2*)&C[p1] = make_float2(v2, v3);
        }
    }
}

// ---------------- launcher ----------------
extern "C" void kernel_launch(void* const* d_in, const int* in_sizes, int n_in,
                              void* d_out, int out_size)
{
    const float* x      = (const float*)d_in[0];
    const float* ln_g   = (const float*)d_in[1];
    const float* ln_b   = (const float*)d_in[2];
    const float* rw     = (const float*)d_in[3];
    const float* rb     = (const float*)d_in[4];
    const float* ew1    = (const float*)d_in[5];
    const float* eb1    = (const float*)d_in[6];
    const float* ew2    = (const float*)d_in[7];
    const float* eb2    = (const float*)d_in[8];
    const float* sw1    = (const float*)d_in[9];
    const float* sb1    = (const float*)d_in[10];
    const float* sw2    = (const float*)d_in[11];
    const float* sb2    = (const float*)d_in[12];
    const float* ffln_g = (const float*)d_in[13];
    const float* ffln_b = (const float*)d_in[14];
    const float* ffw1   = (const float*)d_in[15];
    const float* ffb1   = (const float*)d_in[16];
    const float* ffw2   = (const float*)d_in[17];
    const float* ffb2   = (const float*)d_in[18];
    float* out = (float*)d_out;

    void* p;
    cudaGetSymbolAddress(&p, g_h);     float* ph     = (float*)p;
    cudaGetSymbolAddress(&p, g_mix);   float* pmix   = (float*)p;
    cudaGetSymbolAddress(&p, g_fh);    float* pfh    = (float*)p;
    cudaGetSymbolAddress(&p, g_sact);  float* psact  = (float*)p;
    cudaGetSymbolAddress(&p, g_ffact); float* pffact = (float*)p;
    cudaGetSymbolAddress(&p, g_act1);  float* pact1  = (float*)p;
    cudaGetSymbolAddress(&p, g_y);     float* py     = (float*)p;
    cudaGetSymbolAddress(&p, g_ew1T);  float* pew1T  = (float*)p;
    cudaGetSymbolAddress(&p, g_ew2T);  float* pew2T  = (float*)p;
    cudaGetSymbolAddress(&p, g_sw1T);  float* psw1T  = (float*)p;
    cudaGetSymbolAddress(&p, g_sw2T);  float* psw2T  = (float*)p;
    cudaGetSymbolAddress(&p, g_ffw1T); float* pffw1T = (float*)p;
    cudaGetSymbolAddress(&p, g_ffw2T); float* pffw2T = (float*)p;

    cudaFuncSetAttribute(mm_gemm<0, true,  true >, cudaFuncAttributeMaxDynamicSharedMemorySize, SMEM_TOTAL);
    cudaFuncSetAttribute(mm_gemm<2, false, true >, cudaFuncAttributeMaxDynamicSharedMemorySize, SMEM_TOTAL);
    cudaFuncSetAttribute(mm_gemm<0, false, false>, cudaFuncAttributeMaxDynamicSharedMemorySize, SMEM_TOTAL);
    cudaFuncSetAttribute(mm_gemm<1, false, false>, cudaFuncAttributeMaxDynamicSharedMemorySize, SMEM_TOTAL);
    cudaFuncSetAttribute(mm_gemm<3, false, false>, cudaFuncAttributeMaxDynamicSharedMemorySize, SMEM_TOTAL);

    // weight transposes ([K][N] -> [N][K]) with tf32 rounding
    dim3 tb(32, 8);
    transpose_kernel<<<dim3(DHID/32, DMODEL/32, NEXP), tb>>>(ew1, pew1T, DMODEL, DHID);
    transpose_kernel<<<dim3(DMODEL/32, DHID/32, NEXP), tb>>>(ew2, pew2T, DHID, DMODEL);
    transpose_kernel<<<dim3(DSH/32,   DMODEL/32, 1),   tb>>>(sw1, psw1T, DMODEL, DSH);
    transpose_kernel<<<dim3(DMODEL/32, DSH/32,   1),   tb>>>(sw2, psw2T, DSH, DMODEL);
    transpose_kernel<<<dim3(DHID/32,  DMODEL/32, 1),   tb>>>(ffw1, pffw1T, DMODEL, DHID);
    transpose_kernel<<<dim3(DMODEL/32, DHID/32,  1),   tb>>>(ffw2, pffw2T, DHID, DMODEL);

    zero_cnt_kernel<<<1, 32>>>();
    ln_kernel<true><<<TOKS, 128>>>(x, ln_g, ln_b, rw, rb, ph);
    setup_kernel<<<1, 256>>>();
    scatter_kernel<<<TOKS/256, 256>>>();

    // expert GEMM1 + SiLU (gathered A rows)
    mm_gemm<0, true, true><<<dim3(MAX_TILES, DHID/BN), 256, SMEM_TOTAL>>>(
        ph, pew1T, eb1, pact1, DMODEL, DHID, nullptr, nullptr, 1.0f);
    // expert GEMM2
    mm_gemm<2, false, true><<<dim3(MAX_TILES, DMODEL/BN), 256, SMEM_TOTAL>>>(
        pact1, pew2T, eb2, py, DHID, DMODEL, nullptr, nullptr, 1.0f);
    // shared expert
    mm_gemm<0, false, false><<<dim3(TOKS/BM, DSH/BN), 256, SMEM_TOTAL>>>(
        ph, psw1T, sb1, psact, DMODEL, DSH, nullptr, nullptr, 1.0f);
    mm_gemm<1, false, false><<<dim3(TOKS/BM, DMODEL/BN), 256, SMEM_TOTAL>>>(
        psact, psw2T, sb2, pmix, DSH, DMODEL, nullptr, nullptr, SHARED_SCALE);
    combine_kernel<<<TOKS, 128>>>();
    // final FF
    ln_kernel<false><<<TOKS, 128>>>(pmix, ffln_g, ffln_b, nullptr, nullptr, pfh);
    mm_gemm<0, false, false><<<dim3(TOKS/BM, DHID/BN), 256, SMEM_TOTAL>>>(
        pfh, pffw1T, ffb1, pffact, DMODEL, DHID, nullptr, nullptr, 1.0f);
    mm_gemm<3, false, false><<<dim3(TOKS/BM, DMODEL/BN), 256, SMEM_TOTAL>>>(
        pffact, pffw2T, ffb2, out, DHID, DMODEL, x, pmix, 1.0f);
}

// round 4
// speedup vs baseline: 5.1011x; 1.5291x over previous
#include <cuda_runtime.h>
#include <cuda_fp16.h>
#include <cstdint>
#include <cstddef>

// ---------------- problem constants ----------------
#define TOKS 4096
#define DMODEL 512
#define NEXP 16
#define DHID 2048
#define DSH  1024
#define INV_TEMP (1.0f/0.7f)
#define LN_EPS 1e-5f
#define SHARED_SCALE 0.25f

#define BM 128
#define BN 128
#define BKH 64                      // fp16 k per stage chunk
#define MAX_TILES 80
#define PADMAX (MAX_TILES*BM)

// stage: A 128x64 fp16 (16KB) + B 64x128 fp16 (16KB)
#define STAGE_BYTES 32768
#define SMEM_TOTAL (2*STAGE_BYTES)
#define B_SMEM_OFF 16384

// ---------------- device scratch ----------------
__device__ __half g_h[TOKS*DMODEL];
__device__ float  g_mix[TOKS*DMODEL];
__device__ __half g_fh[TOKS*DMODEL];
__device__ __half g_sact[TOKS*DSH];
__device__ __half g_ffact[(size_t)TOKS*DHID];
__device__ __half g_act1[(size_t)PADMAX*DHID];
__device__ float  g_y[(size_t)PADMAX*DMODEL];
__device__ int    g_cnt[NEXP];
__device__ int    g_fill[NEXP];
__device__ int    g_off[NEXP];
__device__ int    g_tile_e[MAX_TILES];
__device__ int    g_perm_tok[PADMAX];
__device__ int    g_top_i[TOKS*2];
__device__ float  g_top_w[TOKS*2];
__device__ int    g_apos[TOKS*2];
// fp16 weights, SAME layout as input ([K][N], n-contiguous)
__device__ __half g_ew1h[(size_t)NEXP*DMODEL*DHID];
__device__ __half g_ew2h[(size_t)NEXP*DHID*DMODEL];
__device__ __half g_sw1h[(size_t)DMODEL*DSH];
__device__ __half g_sw2h[(size_t)DSH*DMODEL];
__device__ __half g_ffw1h[(size_t)DMODEL*DHID];
__device__ __half g_ffw2h[(size_t)DHID*DMODEL];

__device__ __forceinline__ float silu(float v) {
    return v * (1.0f / (1.0f + __expf(-v)));
}
__device__ __forceinline__ uint32_t smem_u32(const void* p) {
    uint32_t a;
    asm("{ .reg .u64 t; cvta.to.shared.u64 t, %1; cvt.u32.u64 %0, t; }" : "=r"(a) : "l"(p));
    return a;
}
__device__ __forceinline__ void cp16(uint32_t dst, const void* src, int sz) {
    asm volatile("cp.async.cg.shared.global [%0], [%1], 16, %2;"
        :: "r"(dst), "l"(src), "r"(sz) : "memory");
}
#define CP_COMMIT() asm volatile("cp.async.commit_group;" ::: "memory")
#define CP_WAIT1()  asm volatile("cp.async.wait_group 1;" ::: "memory")
#define LDSM_X4(r0,r1,r2,r3,addr) \
    asm volatile("ldmatrix.sync.aligned.m8n8.x4.shared.b16 {%0,%1,%2,%3}, [%4];" \
        : "=r"(r0),"=r"(r1),"=r"(r2),"=r"(r3) : "r"(addr))
#define LDSM_X4_T(r0,r1,r2,r3,addr) \
    asm volatile("ldmatrix.sync.aligned.m8n8.x4.trans.shared.b16 {%0,%1,%2,%3}, [%4];" \
        : "=r"(r0),"=r"(r1),"=r"(r2),"=r"(r3) : "r"(addr))

__device__ __forceinline__ void mma_f16(float* c, const uint32_t* a, const uint32_t* b) {
    asm volatile(
        "mma.sync.aligned.m16n8k16.row.col.f32.f16.f16.f32 "
        "{%0,%1,%2,%3}, {%4,%5,%6,%7}, {%8,%9}, {%0,%1,%2,%3};"
        : "+f"(c[0]), "+f"(c[1]), "+f"(c[2]), "+f"(c[3])
        : "r"(a[0]), "r"(a[1]), "r"(a[2]), "r"(a[3]), "r"(b[0]), "r"(b[1]));
}

// ---------------- small kernels ----------------
__global__ void zero_cnt_kernel() {
    if (threadIdx.x < NEXP) g_cnt[threadIdx.x] = 0;
}

// fp32 -> fp16 elementwise (n divisible by 1024)
__global__ void __launch_bounds__(256) cvt_half_kernel(
    const float* __restrict__ in, __half* __restrict__ out)
{
    int i = (blockIdx.x * 256 + threadIdx.x) * 4;
    float4 v = *(const float4*)&in[i];
    __half2 h0 = __floats2half2_rn(v.x, v.y);
    __half2 h1 = __floats2half2_rn(v.z, v.w);
    *(__half2*)&out[i]     = h0;
    *(__half2*)&out[i + 2] = h1;
}

template<bool ROUTER>
__global__ void __launch_bounds__(128) ln_kernel(
    const float* __restrict__ x,
    const float* __restrict__ gamma, const float* __restrict__ beta,
    const float* __restrict__ rw, const float* __restrict__ rb,
    __half* __restrict__ out)
{
    int tok = blockIdx.x, tid = threadIdx.x;
    __shared__ float hs[DMODEL];
    __shared__ float red[2][4];
    __shared__ float logits[NEXP];

    float4 v = *(const float4*)&x[(size_t)tok*DMODEL + tid*4];
    float s = v.x+v.y+v.z+v.w;
    float q = v.x*v.x+v.y*v.y+v.z*v.z+v.w*v.w;
    #pragma unroll
    for (int o = 16; o; o >>= 1) {
        s += __shfl_xor_sync(0xffffffffu, s, o);
        q += __shfl_xor_sync(0xffffffffu, q, o);
    }
    if ((tid & 31) == 0) { red[0][tid>>5] = s; red[1][tid>>5] = q; }
    __syncthreads();
    s = red[0][0]+red[0][1]+red[0][2]+red[0][3];
    q = red[1][0]+red[1][1]+red[1][2]+red[1][3];
    float mu  = s * (1.0f/DMODEL);
    float var = q * (1.0f/DMODEL) - mu*mu;
    float rs  = rsqrtf(var + LN_EPS);

    int d = tid*4;
    float o0 = (v.x-mu)*rs*gamma[d+0] + beta[d+0];
    float o1 = (v.y-mu)*rs*gamma[d+1] + beta[d+1];
    float o2 = (v.z-mu)*rs*gamma[d+2] + beta[d+2];
    float o3 = (v.w-mu)*rs*gamma[d+3] + beta[d+3];
    *(__half2*)&out[(size_t)tok*DMODEL + d]     = __floats2half2_rn(o0, o1);
    *(__half2*)&out[(size_t)tok*DMODEL + d + 2] = __floats2half2_rn(o2, o3);

    if (ROUTER) {
        hs[d+0] = o0; hs[d+1] = o1; hs[d+2] = o2; hs[d+3] = o3;
        __syncthreads();
        if (tid < NEXP) {
            float acc = 0.0f;
            #pragma unroll 8
            for (int dd = 0; dd < DMODEL; dd++) acc += hs[dd] * rw[dd*NEXP + tid];
            logits[tid] = (acc + rb[tid]) * INV_TEMP;
        }
        __syncthreads();
        if (tid == 0) {
            float m = logits[0];
            #pragma unroll
            for (int e = 1; e < NEXP; e++) m = fmaxf(m, logits[e]);
            float p[NEXP]; float sum = 0.0f;
            #pragma unroll
            for (int e = 0; e < NEXP; e++) { p[e] = __expf(logits[e]-m); sum += p[e]; }
            float inv = 1.0f / sum;
            int i0 = 0; float b0 = p[0];
            #pragma unroll
            for (int e = 1; e < NEXP; e++) if (p[e] > b0) { b0 = p[e]; i0 = e; }
            int i1 = -1; float b1 = -1.0f;
            #pragma unroll
            for (int e = 0; e < NEXP; e++) if (e != i0 && p[e] > b1) { b1 = p[e]; i1 = e; }
            g_top_i[tok*2+0] = i0; g_top_i[tok*2+1] = i1;
            g_top_w[tok*2+0] = b0*inv; g_top_w[tok*2+1] = b1*inv;
            atomicAdd(&g_cnt[i0], 1);
            atomicAdd(&g_cnt[i1], 1);
        }
    }
}

__global__ void setup_kernel() {
    int tid = threadIdx.x;
    for (int i = tid; i < PADMAX; i += blockDim.x) g_perm_tok[i] = -1;
    if (tid < MAX_TILES) g_tile_e[tid] = -1;
    if (tid < NEXP) g_fill[tid] = 0;
    __syncthreads();
    if (tid == 0) {
        int running = 0;
        for (int e = 0; e < NEXP; e++) {
            g_off[e] = running;
            int nt = (g_cnt[e] + BM - 1) / BM;
            int t0 = running / BM;
            for (int t = 0; t < nt; t++) g_tile_e[t0 + t] = e;
            running += nt * BM;
        }
    }
}

__global__ void scatter_kernel() {
    int tok = blockIdx.x * blockDim.x + threadIdx.x;
    if (tok >= TOKS) return;
    #pragma unroll
    for (int k = 0; k < 2; k++) {
        int e = g_top_i[tok*2+k];
        int pos = atomicAdd(&g_fill[e], 1);
        int gp = g_off[e] + pos;
        g_perm_tok[gp] = tok;
        g_apos[tok*2+k] = gp;
    }
}

__global__ void __launch_bounds__(128) combine_kernel() {
    int tok = blockIdx.x, tid = threadIdx.x;
    int d = tid*4;
    int g0 = g_apos[tok*2+0], g1 = g_apos[tok*2+1];
    float w0 = g_top_w[tok*2+0], w1 = g_top_w[tok*2+1];
    float4 m = *(float4*)&g_mix[(size_t)tok*DMODEL + d];
    float4 a = *(const float4*)&g_y[(size_t)g0*DMODEL + d];
    float4 b = *(const float4*)&g_y[(size_t)g1*DMODEL + d];
    m.x += w0*a.x + w1*b.x;
    m.y += w0*a.y + w1*b.y;
    m.z += w0*a.z + w1*b.z;
    m.w += w0*a.w + w1*b.w;
    *(float4*)&g_mix[(size_t)tok*DMODEL + d] = m;
}

// ---------------- fp16 mma.sync GEMM ----------------
// C[128x128] = epi(A[M,K]h @ B[K,N]h + bias)
// A: fp16 k-contiguous. B: fp16 [K][N] n-contiguous (ldmatrix.trans).
// EPI: 0 = silu -> fp16 C, 1 = *scale -> fp32, 2 = store fp32, 3 = +r1+r2 fp32
template<int EPI, bool GATHER, bool EXPERT>
__global__ void __launch_bounds__(256) mm_gemm(
    const __half* __restrict__ A, const __half* __restrict__ B,
    const float* __restrict__ bias, void* __restrict__ Cv,
    int K, int N,
    const float* __restrict__ r1, const float* __restrict__ r2, float scale)
{
    extern __shared__ char smem[];
    const uint32_t sbase = smem_u32(smem);
    const int tid = threadIdx.x;
    const int wid = tid >> 5, lid = tid & 31;
    const int row0 = blockIdx.x * BM;
    const int col0 = blockIdx.y * BN;

    const __half* Bp = B;
    const float* bp = bias;
    if (EXPERT) {
        int e = g_tile_e[blockIdx.x];
        if (e < 0) return;
        Bp = B + (size_t)e * (size_t)K * N;
        bp = bias + (size_t)e * N;
    }

    // ---- cp.async slots: 4 A chunks + 4 B chunks (16B each) per thread ----
    const __half* asrc[4]; int asz[4]; uint32_t adst[4];
    const __half* bsrc[4]; uint32_t bdst[4];
    #pragma unroll
    for (int i = 0; i < 4; i++) {
        int id = tid + i * 256;
        // A: row 0..127, chunk 0..7 (8 fp16 each)
        int arow = id >> 3, ac = id & 7;
        adst[i] = (uint32_t)(arow * 128 + ((ac ^ (arow & 7)) << 4));
        if (GATHER) {
            int t = g_perm_tok[row0 + arow];
            asrc[i] = (t >= 0) ? (A + (size_t)t * K + ac * 8) : A;
            asz[i]  = (t >= 0) ? 16 : 0;
        } else {
            asrc[i] = A + (size_t)(row0 + arow) * K + ac * 8;
            asz[i]  = 16;
        }
        // B: k-row 0..63, n-chunk 0..15
        int krow = id >> 4, bc = id & 15;
        int bcs = (bc & 8) | ((bc ^ krow) & 7);
        bdst[i] = (uint32_t)(B_SMEM_OFF + krow * 256 + (bcs << 4));
        bsrc[i] = Bp + (size_t)krow * N + col0 + bc * 8;
    }
    const size_t bstep = (size_t)BKH * N;   // B advance per k-chunk (elems)

    // ---- fragment addressing ----
    const int wm = wid & 1;     // m half (64)
    const int wn = wid >> 1;    // n quarter (32)
    const uint32_t xorA = (uint32_t)(lid & 7);
    const uint32_t ahi  = (uint32_t)(lid >> 4);          // A k-chunk bit
    uint32_t abase[4];
    #pragma unroll
    for (int mt = 0; mt < 4; mt++)
        abase[mt] = (uint32_t)((wm*64 + mt*16 + (lid & 15)) * 128);
    // B: lane k-row part + per-pair swizzled n-chunk
    const uint32_t browp = (uint32_t)((((lid >> 3) & 1) * 8 + (lid & 7)) * 256);
    uint32_t bcs2[2];
    #pragma unroll
    for (int pr = 0; pr < 2; pr++) {
        uint32_t c = (uint32_t)(wn*4 + pr*2) + (uint32_t)(lid >> 4);
        bcs2[pr] = ((c & 8) | ((c ^ xorA) & 7)) << 4;
    }

    float acc[4][4][4];
    #pragma unroll
    for (int mt = 0; mt < 4; mt++)
        #pragma unroll
        for (int nt = 0; nt < 4; nt++)
            #pragma unroll
            for (int u = 0; u < 4; u++) acc[mt][nt][u] = 0.0f;

    const int nst = K / BKH;

    // prologue
    #pragma unroll
    for (int s = 0; s < 2; s++) {
        uint32_t sb = sbase + s * STAGE_BYTES;
        #pragma unroll
        for (int i = 0; i < 4; i++) cp16(sb + adst[i], asrc[i] + s*BKH, asz[i]);
        #pragma unroll
        for (int i = 0; i < 4; i++) cp16(sb + bdst[i], bsrc[i] + s*bstep, 16);
        CP_COMMIT();
    }

    for (int c = 0; c < nst; c++) {
        CP_WAIT1();
        __syncthreads();
        uint32_t sb = sbase + (c & 1) * STAGE_BYTES;

        #pragma unroll
        for (int kc = 0; kc < 4; kc++) {
            uint32_t af[4][4];
            #pragma unroll
            for (int mt = 0; mt < 4; mt++) {
                uint32_t addr = sb + abase[mt] +
                    ((((uint32_t)(kc*2) + ahi) ^ xorA) << 4);
                LDSM_X4(af[mt][0], af[mt][1], af[mt][2], af[mt][3], addr);
            }
            uint32_t bf[2][4];
            #pragma unroll
            for (int pr = 0; pr < 2; pr++) {
                uint32_t addr = sb + B_SMEM_OFF + (uint32_t)(kc * 4096) + browp + bcs2[pr];
                LDSM_X4_T(bf[pr][0], bf[pr][1], bf[pr][2], bf[pr][3], addr);
            }
            #pragma unroll
            for (int mt = 0; mt < 4; mt++)
                #pragma unroll
                for (int nt = 0; nt < 4; nt++)
                    mma_f16(acc[mt][nt], af[mt], &bf[nt >> 1][(nt & 1) * 2]);
        }
        __syncthreads();

        int nx = c + 2;
        if (nx < nst) {
            uint32_t sb2 = sbase + (nx & 1) * STAGE_BYTES;
            #pragma unroll
            for (int i = 0; i < 4; i++) cp16(sb2 + adst[i], asrc[i] + nx*BKH, asz[i]);
            #pragma unroll
            for (int i = 0; i < 4; i++) cp16(sb2 + bdst[i], bsrc[i] + nx*bstep, 16);
        }
        CP_COMMIT();
    }

    // ---- epilogue ----
    const int g = lid >> 2, t = lid & 3;
    #pragma unroll
    for (int mt = 0; mt < 4; mt++) {
        int rA = row0 + wm*64 + mt*16 + g;
        #pragma unroll
        for (int nt = 0; nt < 4; nt++) {
            int cb = col0 + wn*32 + nt*8 + t*2;
            float bb0 = bp[cb], bb1 = bp[cb + 1];
            float v0 = acc[mt][nt][0] + bb0;
            float v1 = acc[mt][nt][1] + bb1;
            float v2 = acc[mt][nt][2] + bb0;
            float v3 = acc[mt][nt][3] + bb1;
            size_t p0 = (size_t)rA * N + cb;
            size_t p1 = (size_t)(rA + 8) * N + cb;
            if (EPI == 0) {
                __half* C = (__half*)Cv;
                *(__half2*)&C[p0] = __floats2half2_rn(silu(v0), silu(v1));
                *(__half2*)&C[p1] = __floats2half2_rn(silu(v2), silu(v3));
            } else {
                float* C = (float*)Cv;
                if (EPI == 1) { v0 *= scale; v1 *= scale; v2 *= scale; v3 *= scale; }
                else if (EPI == 3) {
                    v0 += r1[p0]   + r2[p0];
                    v1 += r1[p0+1] + r2[p0+1];
                    v2 += r1[p1]   + r2[p1];
                    v3 += r1[p1+1] + r2[p1+1];
                }
                *(float2*)&C[p0] = make_float2(v0, v1);
                *(float2*)&C[p1] = make_float2(v2, v3);
            }
        }
    }
}

// ---------------- launcher ----------------
extern "C" void kernel_launch(void* const* d_in, const int* in_sizes, int n_in,
                              void* d_out, int out_size)
{
    const float* x      = (const float*)d_in[0];
    const float* ln_g   = (const float*)d_in[1];
    const float* ln_b   = (const float*)d_in[2];
    const float* rw     = (const float*)d_in[3];
    const float* rb     = (const float*)d_in[4];
    const float* ew1    = (const float*)d_in[5];
    const float* eb1    = (const float*)d_in[6];
    const float* ew2    = (const float*)d_in[7];
    const float* eb2    = (const float*)d_in[8];
    const float* sw1    = (const float*)d_in[9];
    const float* sb1    = (const float*)d_in[10];
    const float* sw2    = (const float*)d_in[11];
    const float* sb2    = (const float*)d_in[12];
    const float* ffln_g = (const float*)d_in[13];
    const float* ffln_b = (const float*)d_in[14];
    const float* ffw1   = (const float*)d_in[15];
    const float* ffb1   = (const float*)d_in[16];
    const float* ffw2   = (const float*)d_in[17];
    const float* ffb2   = (const float*)d_in[18];
    float* out = (float*)d_out;

    void* p;
    cudaGetSymbolAddress(&p, g_h);     __half* ph     = (__half*)p;
    cudaGetSymbolAddress(&p, g_mix);   float*  pmix   = (float*)p;
    cudaGetSymbolAddress(&p, g_fh);    __half* pfh    = (__half*)p;
    cudaGetSymbolAddress(&p, g_sact);  __half* psact  = (__half*)p;
    cudaGetSymbolAddress(&p, g_ffact); __half* pffact = (__half*)p;
    cudaGetSymbolAddress(&p, g_act1);  __half* pact1  = (__half*)p;
    cudaGetSymbolAddress(&p, g_y);     float*  py     = (float*)p;
    cudaGetSymbolAddress(&p, g_ew1h);  __half* pew1h  = (__half*)p;
    cudaGetSymbolAddress(&p, g_ew2h);  __half* pew2h  = (__half*)p;
    cudaGetSymbolAddress(&p, g_sw1h);  __half* psw1h  = (__half*)p;
    cudaGetSymbolAddress(&p, g_sw2h);  __half* psw2h  = (__half*)p;
    cudaGetSymbolAddress(&p, g_ffw1h); __half* pffw1h = (__half*)p;
    cudaGetSymbolAddress(&p, g_ffw2h); __half* pffw2h = (__half*)p;

    cudaFuncSetAttribute(mm_gemm<0, true,  true >, cudaFuncAttributeMaxDynamicSharedMemorySize, SMEM_TOTAL);
    cudaFuncSetAttribute(mm_gemm<2, false, true >, cudaFuncAttributeMaxDynamicSharedMemorySize, SMEM_TOTAL);
    cudaFuncSetAttribute(mm_gemm<0, false, false>, cudaFuncAttributeMaxDynamicSharedMemorySize, SMEM_TOTAL);
    cudaFuncSetAttribute(mm_gemm<1, false, false>, cudaFuncAttributeMaxDynamicSharedMemorySize, SMEM_TOTAL);
    cudaFuncSetAttribute(mm_gemm<3, false, false>, cudaFuncAttributeMaxDynamicSharedMemorySize, SMEM_TOTAL);

    // fp32 -> fp16 weight conversion (layout preserved, coalesced)
    cvt_half_kernel<<<(NEXP*DMODEL*DHID)/1024, 256>>>(ew1, pew1h);
    cvt_half_kernel<<<(NEXP*DHID*DMODEL)/1024, 256>>>(ew2, pew2h);
    cvt_half_kernel<<<(DMODEL*DSH)/1024, 256>>>(sw1, psw1h);
    cvt_half_kernel<<<(DSH*DMODEL)/1024, 256>>>(sw2, psw2h);
    cvt_half_kernel<<<(DMODEL*DHID)/1024, 256>>>(ffw1, pffw1h);
    cvt_half_kernel<<<(DHID*DMODEL)/1024, 256>>>(ffw2, pffw2h);

    zero_cnt_kernel<<<1, 32>>>();
    ln_kernel<true><<<TOKS, 128>>>(x, ln_g, ln_b, rw, rb, ph);
    setup_kernel<<<1, 256>>>();
    scatter_kernel<<<TOKS/256, 256>>>();

    // expert GEMM1 + SiLU (gathered A rows) -> fp16
    mm_gemm<0, true, true><<<dim3(MAX_TILES, DHID/BN), 256, SMEM_TOTAL>>>(
        ph, pew1h, eb1, pact1, DMODEL, DHID, nullptr, nullptr, 1.0f);
    // expert GEMM2 -> fp32 y
    mm_gemm<2, false, true><<<dim3(MAX_TILES, DMODEL/BN), 256, SMEM_TOTAL>>>(
        pact1, pew2h, eb2, py, DHID, DMODEL, nullptr, nullptr, 1.0f);
    // shared expert
    mm_gemm<0, false, false><<<dim3(TOKS/BM, DSH/BN), 256, SMEM_TOTAL>>>(
        ph, psw1h, sb1, psact, DMODEL, DSH, nullptr, nullptr, 1.0f);
    mm_gemm<1, false, false><<<dim3(TOKS/BM, DMODEL/BN), 256, SMEM_TOTAL>>>(
        psact, psw2h, sb2, pmix, DSH, DMODEL, nullptr, nullptr, SHARED_SCALE);
    combine_kernel<<<TOKS, 128>>>();
    // final FF
    ln_kernel<false><<<TOKS, 128>>>(pmix, ffln_g, ffln_b, nullptr, nullptr, pfh);
    mm_gemm<0, false, false><<<dim3(TOKS/BM, DHID/BN), 256, SMEM_TOTAL>>>(
        pfh, pffw1h, ffb1, pffact, DMODEL, DHID, nullptr, nullptr, 1.0f);
    mm_gemm<3, false, false><<<dim3(TOKS/BM, DMODEL/BN), 256, SMEM_TOTAL>>>(
        pffact, pffw2h, ffb2, out, DHID, DMODEL, x, pmix, 1.0f);
}

// round 5
// speedup vs baseline: 5.3582x; 1.0504x over previous
#include <cuda_runtime.h>
#include <cuda_fp16.h>
#include <cstdint>
#include <cstddef>

// ---------------- problem constants ----------------
#define TOKS 4096
#define DMODEL 512
#define NEXP 16
#define DHID 2048
#define DSH  1024
#define INV_TEMP (1.0f/0.7f)
#define LN_EPS 1e-5f
#define SHARED_SCALE 0.25f

#define BM 128
#define BN 128
#define BKH 64
#define MAX_TILES 80
#define PADMAX (MAX_TILES*BM)

#define NSTAGE 3
#define STAGE_BYTES 32768           // A 128x64 fp16 + B 64x128 fp16
#define SMEM_TOTAL (NSTAGE*STAGE_BYTES)
#define B_SMEM_OFF 16384

// ---------------- device scratch ----------------
__device__ __half g_h[TOKS*DMODEL];
__device__ float  g_mix[TOKS*DMODEL];
__device__ __half g_fh[TOKS*DMODEL];
__device__ __half g_sact[TOKS*DSH];
__device__ __half g_ffact[(size_t)TOKS*DHID];
__device__ __half g_act1[(size_t)PADMAX*DHID];
__device__ float  g_y[(size_t)PADMAX*DMODEL];
__device__ int    g_tile_e[MAX_TILES];
__device__ int    g_perm_tok[PADMAX];
__device__ int    g_top_i[TOKS*2];
__device__ float  g_top_w[TOKS*2];
__device__ int    g_apos[TOKS*2];
// fp16 weights, same layout as inputs ([K][N], n-contiguous)
__device__ __half g_ew1h[(size_t)NEXP*DMODEL*DHID];
__device__ __half g_ew2h[(size_t)NEXP*DHID*DMODEL];
__device__ __half g_sw1h[(size_t)DMODEL*DSH];
__device__ __half g_sw2h[(size_t)DSH*DMODEL];
__device__ __half g_ffw1h[(size_t)DMODEL*DHID];
__device__ __half g_ffw2h[(size_t)DHID*DMODEL];

__device__ __forceinline__ float silu(float v) {
    return v * (1.0f / (1.0f + __expf(-v)));
}
__device__ __forceinline__ uint32_t smem_u32(const void* p) {
    uint32_t a;
    asm("{ .reg .u64 t; cvta.to.shared.u64 t, %1; cvt.u32.u64 %0, t; }" : "=r"(a) : "l"(p));
    return a;
}
__device__ __forceinline__ void cp16(uint32_t dst, const void* src, int sz) {
    asm volatile("cp.async.cg.shared.global [%0], [%1], 16, %2;"
        :: "r"(dst), "l"(src), "r"(sz) : "memory");
}
#define CP_COMMIT() asm volatile("cp.async.commit_group;" ::: "memory")
#define CP_WAIT2()  asm volatile("cp.async.wait_group 2;" ::: "memory")
#define LDSM_X4(r0,r1,r2,r3,addr) \
    asm volatile("ldmatrix.sync.aligned.m8n8.x4.shared.b16 {%0,%1,%2,%3}, [%4];" \
        : "=r"(r0),"=r"(r1),"=r"(r2),"=r"(r3) : "r"(addr))
#define LDSM_X4_T(r0,r1,r2,r3,addr) \
    asm volatile("ldmatrix.sync.aligned.m8n8.x4.trans.shared.b16 {%0,%1,%2,%3}, [%4];" \
        : "=r"(r0),"=r"(r1),"=r"(r2),"=r"(r3) : "r"(addr))

__device__ __forceinline__ void mma_f16(float* c, const uint32_t* a, const uint32_t* b) {
    asm volatile(
        "mma.sync.aligned.m16n8k16.row.col.f32.f16.f16.f32 "
        "{%0,%1,%2,%3}, {%4,%5,%6,%7}, {%8,%9}, {%0,%1,%2,%3};"
        : "+f"(c[0]), "+f"(c[1]), "+f"(c[2]), "+f"(c[3])
        : "r"(a[0]), "r"(a[1]), "r"(a[2]), "r"(a[3]), "r"(b[0]), "r"(b[1]));
}

// ---------------- fused fp32->fp16 weight conversion ----------------
// segments (element counts): ew1 16777216 | ew2 16777216 | sw1 524288 |
// sw2 524288 | ffw1 1048576 | ffw2 1048576 ; total 36700160 = 35840*1024
__global__ void __launch_bounds__(256) cvt_all_kernel(
    const float* __restrict__ w0, const float* __restrict__ w1,
    const float* __restrict__ w2, const float* __restrict__ w3,
    const float* __restrict__ w4, const float* __restrict__ w5,
    __half* __restrict__ o0, __half* __restrict__ o1,
    __half* __restrict__ o2, __half* __restrict__ o3,
    __half* __restrict__ o4, __half* __restrict__ o5)
{
    size_t i = ((size_t)blockIdx.x * 256 + threadIdx.x) * 4;
    const float* src; __half* dst; size_t off;
    if      (i < 16777216ull) { src = w0; dst = o0; off = i; }
    else if (i < 33554432ull) { src = w1; dst = o1; off = i - 16777216ull; }
    else if (i < 34078720ull) { src = w2; dst = o2; off = i - 33554432ull; }
    else if (i < 34603008ull) { src = w3; dst = o3; off = i - 34078720ull; }
    else if (i < 35651584ull) { src = w4; dst = o4; off = i - 34603008ull; }
    else                      { src = w5; dst = o5; off = i - 35651584ull; }
    float4 v = *(const float4*)&src[off];
    *(__half2*)&dst[off]     = __floats2half2_rn(v.x, v.y);
    *(__half2*)&dst[off + 2] = __floats2half2_rn(v.z, v.w);
}

// ---------------- LayerNorm kernels ----------------
// MODE 0: input LN + router top-2 (no atomics; counts done in setup)
// MODE 1: combine (mix += w0*y0 + w1*y1) then LN -> fh
template<int MODE>
__global__ void __launch_bounds__(128) ln_kernel(
    const float* __restrict__ x, float* __restrict__ xw,
    const float* __restrict__ gamma, const float* __restrict__ beta,
    const float* __restrict__ rw, const float* __restrict__ rb,
    __half* __restrict__ out)
{
    int tok = blockIdx.x, tid = threadIdx.x;
    __shared__ float hs[DMODEL];
    __shared__ float red[2][4];
    __shared__ float logits[NEXP];

    int d = tid*4;
    float4 v;
    if (MODE == 1) {
        v = *(const float4*)&xw[(size_t)tok*DMODEL + d];
        int g0 = g_apos[tok*2+0], g1 = g_apos[tok*2+1];
        float w0 = g_top_w[tok*2+0], w1 = g_top_w[tok*2+1];
        float4 a = *(const float4*)&g_y[(size_t)g0*DMODEL + d];
        float4 b = *(const float4*)&g_y[(size_t)g1*DMODEL + d];
        v.x += w0*a.x + w1*b.x;
        v.y += w0*a.y + w1*b.y;
        v.z += w0*a.z + w1*b.z;
        v.w += w0*a.w + w1*b.w;
        *(float4*)&xw[(size_t)tok*DMODEL + d] = v;   // moe_out kept for residual
    } else {
        v = *(const float4*)&x[(size_t)tok*DMODEL + d];
    }

    float s = v.x+v.y+v.z+v.w;
    float q = v.x*v.x+v.y*v.y+v.z*v.z+v.w*v.w;
    #pragma unroll
    for (int o = 16; o; o >>= 1) {
        s += __shfl_xor_sync(0xffffffffu, s, o);
        q += __shfl_xor_sync(0xffffffffu, q, o);
    }
    if ((tid & 31) == 0) { red[0][tid>>5] = s; red[1][tid>>5] = q; }
    __syncthreads();
    s = red[0][0]+red[0][1]+red[0][2]+red[0][3];
    q = red[1][0]+red[1][1]+red[1][2]+red[1][3];
    float mu  = s * (1.0f/DMODEL);
    float var = q * (1.0f/DMODEL) - mu*mu;
    float rs  = rsqrtf(var + LN_EPS);

    float o0 = (v.x-mu)*rs*gamma[d+0] + beta[d+0];
    float o1 = (v.y-mu)*rs*gamma[d+1] + beta[d+1];
    float o2 = (v.z-mu)*rs*gamma[d+2] + beta[d+2];
    float o3 = (v.w-mu)*rs*gamma[d+3] + beta[d+3];
    *(__half2*)&out[(size_t)tok*DMODEL + d]     = __floats2half2_rn(o0, o1);
    *(__half2*)&out[(size_t)tok*DMODEL + d + 2] = __floats2half2_rn(o2, o3);

    if (MODE == 0) {
        hs[d+0] = o0; hs[d+1] = o1; hs[d+2] = o2; hs[d+3] = o3;
        __syncthreads();
        if (tid < NEXP) {
            float acc = 0.0f;
            #pragma unroll 8
            for (int dd = 0; dd < DMODEL; dd++) acc += hs[dd] * rw[dd*NEXP + tid];
            logits[tid] = (acc + rb[tid]) * INV_TEMP;
        }
        __syncthreads();
        if (tid == 0) {
            float m = logits[0];
            #pragma unroll
            for (int e = 1; e < NEXP; e++) m = fmaxf(m, logits[e]);
            float p[NEXP]; float sum = 0.0f;
            #pragma unroll
            for (int e = 0; e < NEXP; e++) { p[e] = __expf(logits[e]-m); sum += p[e]; }
            float inv = 1.0f / sum;
            int i0 = 0; float b0 = p[0];
            #pragma unroll
            for (int e = 1; e < NEXP; e++) if (p[e] > b0) { b0 = p[e]; i0 = e; }
            int i1 = -1; float b1 = -1.0f;
            #pragma unroll
            for (int e = 0; e < NEXP; e++) if (e != i0 && p[e] > b1) { b1 = p[e]; i1 = e; }
            g_top_i[tok*2+0] = i0; g_top_i[tok*2+1] = i1;
            g_top_w[tok*2+0] = b0*inv; g_top_w[tok*2+1] = b1*inv;
        }
    }
}

// ---------------- fused setup + scatter (single block) ----------------
__global__ void __launch_bounds__(256) setup_scatter_kernel() {
    __shared__ int scnt[NEXP];
    __shared__ int soff[NEXP];
    __shared__ int sfill[NEXP];
    int tid = threadIdx.x;

    if (tid < NEXP) { scnt[tid] = 0; sfill[tid] = 0; }
    for (int i = tid; i < PADMAX; i += 256) g_perm_tok[i] = -1;
    if (tid < MAX_TILES) g_tile_e[tid] = -1;
    __syncthreads();

    for (int i = tid; i < TOKS*2; i += 256)
        atomicAdd(&scnt[g_top_i[i]], 1);
    __syncthreads();

    if (tid == 0) {
        int running = 0;
        for (int e = 0; e < NEXP; e++) {
            soff[e] = running;
            int nt = (scnt[e] + BM - 1) / BM;
            int t0 = running / BM;
            for (int t = 0; t < nt; t++) g_tile_e[t0 + t] = e;
            running += nt * BM;
        }
    }
    __syncthreads();

    for (int i = tid; i < TOKS*2; i += 256) {
        int e = g_top_i[i];
        int pos = atomicAdd(&sfill[e], 1);
        int gp = soff[e] + pos;
        g_perm_tok[gp] = i >> 1;
        g_apos[i] = gp;
    }
}

// ---------------- fp16 mma.sync GEMM, 3-stage pipeline ----------------
// EPI: 0 = silu -> fp16, 1 = *scale -> fp32, 2 = store fp32, 3 = +r1+r2 fp32
template<int EPI, bool GATHER, bool EXPERT>
__global__ void __launch_bounds__(256, 2) mm_gemm(
    const __half* __restrict__ A, const __half* __restrict__ B,
    const float* __restrict__ bias, void* __restrict__ Cv,
    int K, int N,
    const float* __restrict__ r1, const float* __restrict__ r2, float scale)
{
    extern __shared__ char smem[];
    const uint32_t sbase = smem_u32(smem);
    const int tid = threadIdx.x;
    const int wid = tid >> 5, lid = tid & 31;
    const int row0 = blockIdx.x * BM;
    const int col0 = blockIdx.y * BN;

    const __half* Bp = B;
    const float* bp = bias;
    if (EXPERT) {
        int e = g_tile_e[blockIdx.x];
        if (e < 0) return;
        Bp = B + (size_t)e * (size_t)K * N;
        bp = bias + (size_t)e * N;
    }

    // ---- cp.async slots: 32-bit element offsets (reg diet) ----
    uint32_t aoff[4]; uint32_t adst[4]; uint32_t amask = 0;
    uint32_t boff[4]; uint32_t bdst[4];
    #pragma unroll
    for (int i = 0; i < 4; i++) {
        int id = tid + i * 256;
        int arow = id >> 3, ac = id & 7;
        adst[i] = (uint32_t)(arow * 128 + ((ac ^ (arow & 7)) << 4));
        if (GATHER) {
            int t = g_perm_tok[row0 + arow];
            aoff[i] = (t >= 0) ? (uint32_t)t * (uint32_t)K + (uint32_t)(ac * 8) : 0u;
            if (t >= 0) amask |= (1u << i);
        } else {
            aoff[i] = (uint32_t)(row0 + arow) * (uint32_t)K + (uint32_t)(ac * 8);
            amask |= (1u << i);
        }
        int krow = id >> 4, bc = id & 15;
        int bcs = (bc & 8) | ((bc ^ krow) & 7);
        bdst[i] = (uint32_t)(B_SMEM_OFF + krow * 256 + (bcs << 4));
        boff[i] = (uint32_t)krow * (uint32_t)N + (uint32_t)(col0 + bc * 8);
    }
    const uint32_t bstep = (uint32_t)BKH * (uint32_t)N;

    // ---- fragment addressing ----
    const int wm = wid & 1;
    const int wn = wid >> 1;
    const uint32_t xorA = (uint32_t)(lid & 7);
    const uint32_t ahi  = (uint32_t)(lid >> 4);
    uint32_t abase[4];
    #pragma unroll
    for (int mt = 0; mt < 4; mt++)
        abase[mt] = (uint32_t)((wm*64 + mt*16 + (lid & 15)) * 128);
    const uint32_t browp = (uint32_t)((((lid >> 3) & 1) * 8 + (lid & 7)) * 256);
    uint32_t bcs2[2];
    #pragma unroll
    for (int pr = 0; pr < 2; pr++) {
        uint32_t c = (uint32_t)(wn*4 + pr*2) + (uint32_t)(lid >> 4);
        bcs2[pr] = ((c & 8) | ((c ^ xorA) & 7)) << 4;
    }

    float acc[4][4][4];
    #pragma unroll
    for (int mt = 0; mt < 4; mt++)
        #pragma unroll
        for (int nt = 0; nt < 4; nt++)
            #pragma unroll
            for (int u = 0; u < 4; u++) acc[mt][nt][u] = 0.0f;

    const int nst = K / BKH;

    // prologue: 3 stages
    #pragma unroll
    for (int s = 0; s < NSTAGE; s++) {
        uint32_t sb = sbase + s * STAGE_BYTES;
        #pragma unroll
        for (int i = 0; i < 4; i++)
            cp16(sb + adst[i], A + aoff[i] + s*BKH, (amask >> i & 1) ? 16 : 0);
        #pragma unroll
        for (int i = 0; i < 4; i++)
            cp16(sb + bdst[i], Bp + boff[i] + s*bstep, 16);
        CP_COMMIT();
    }

    int cb = 0;
    for (int c = 0; c < nst; c++) {
        CP_WAIT2();
        __syncthreads();
        uint32_t sb = sbase + cb * STAGE_BYTES;

        #pragma unroll
        for (int kc = 0; kc < 4; kc++) {
            uint32_t af[4][4];
            #pragma unroll
            for (int mt = 0; mt < 4; mt++) {
                uint32_t addr = sb + abase[mt] +
                    ((((uint32_t)(kc*2) + ahi) ^ xorA) << 4);
                LDSM_X4(af[mt][0], af[mt][1], af[mt][2], af[mt][3], addr);
            }
            uint32_t bf[2][4];
            #pragma unroll
            for (int pr = 0; pr < 2; pr++) {
                uint32_t addr = sb + B_SMEM_OFF + (uint32_t)(kc * 4096) + browp + bcs2[pr];
                LDSM_X4_T(bf[pr][0], bf[pr][1], bf[pr][2], bf[pr][3], addr);
            }
            #pragma unroll
            for (int mt = 0; mt < 4; mt++)
                #pragma unroll
                for (int nt = 0; nt < 4; nt++)
                    mma_f16(acc[mt][nt], af[mt], &bf[nt >> 1][(nt & 1) * 2]);
        }
        __syncthreads();

        int nx = c + NSTAGE;
        if (nx < nst) {
            #pragma unroll
            for (int i = 0; i < 4; i++)
                cp16(sb + adst[i], A + aoff[i] + nx*BKH, (amask >> i & 1) ? 16 : 0);
            #pragma unroll
            for (int i = 0; i < 4; i++)
                cp16(sb + bdst[i], Bp + boff[i] + (uint32_t)nx*bstep, 16);
        }
        CP_COMMIT();
        cb = (cb == NSTAGE-1) ? 0 : cb + 1;
    }

    // ---- epilogue ----
    const int g = lid >> 2, t = lid & 3;
    #pragma unroll
    for (int mt = 0; mt < 4; mt++) {
        int rA = row0 + wm*64 + mt*16 + g;
        #pragma unroll
        for (int nt = 0; nt < 4; nt++) {
            int cb2 = col0 + wn*32 + nt*8 + t*2;
            float bb0 = bp[cb2], bb1 = bp[cb2 + 1];
            float v0 = acc[mt][nt][0] + bb0;
            float v1 = acc[mt][nt][1] + bb1;
            float v2 = acc[mt][nt][2] + bb0;
            float v3 = acc[mt][nt][3] + bb1;
            size_t p0 = (size_t)rA * N + cb2;
            size_t p1 = (size_t)(rA + 8) * N + cb2;
            if (EPI == 0) {
                __half* C = (__half*)Cv;
                *(__half2*)&C[p0] = __floats2half2_rn(silu(v0), silu(v1));
                *(__half2*)&C[p1] = __floats2half2_rn(silu(v2), silu(v3));
            } else {
                float* C = (float*)Cv;
                if (EPI == 1) { v0 *= scale; v1 *= scale; v2 *= scale; v3 *= scale; }
                else if (EPI == 3) {
                    v0 += r1[p0]   + r2[p0];
                    v1 += r1[p0+1] + r2[p0+1];
                    v2 += r1[p1]   + r2[p1];
                    v3 += r1[p1+1] + r2[p1+1];
                }
                *(float2*)&C[p0] = make_float2(v0, v1);
                *(float2*)&C[p1] = make_float2(v2, v3);
            }
        }
    }
}

// ---------------- launcher ----------------
extern "C" void kernel_launch(void* const* d_in, const int* in_sizes, int n_in,
                              void* d_out, int out_size)
{
    const float* x      = (const float*)d_in[0];
    const float* ln_g   = (const float*)d_in[1];
    const float* ln_b   = (const float*)d_in[2];
    const float* rw     = (const float*)d_in[3];
    const float* rb     = (const float*)d_in[4];
    const float* ew1    = (const float*)d_in[5];
    const float* eb1    = (const float*)d_in[6];
    const float* ew2    = (const float*)d_in[7];
    const float* eb2    = (const float*)d_in[8];
    const float* sw1    = (const float*)d_in[9];
    const float* sb1    = (const float*)d_in[10];
    const float* sw2    = (const float*)d_in[11];
    const float* sb2    = (const float*)d_in[12];
    const float* ffln_g = (const float*)d_in[13];
    const float* ffln_b = (const float*)d_in[14];
    const float* ffw1   = (const float*)d_in[15];
    const float* ffb1   = (const float*)d_in[16];
    const float* ffw2   = (const float*)d_in[17];
    const float* ffb2   = (const float*)d_in[18];
    float* out = (float*)d_out;

    void* p;
    cudaGetSymbolAddress(&p, g_h);     __half* ph     = (__half*)p;
    cudaGetSymbolAddress(&p, g_mix);   float*  pmix   = (float*)p;
    cudaGetSymbolAddress(&p, g_fh);    __half* pfh    = (__half*)p;
    cudaGetSymbolAddress(&p, g_sact);  __half* psact  = (__half*)p;
    cudaGetSymbolAddress(&p, g_ffact); __half* pffact = (__half*)p;
    cudaGetSymbolAddress(&p, g_act1);  __half* pact1  = (__half*)p;
    cudaGetSymbolAddress(&p, g_y);     float*  py     = (float*)p;
    cudaGetSymbolAddress(&p, g_ew1h);  __half* pew1h  = (__half*)p;
    cudaGetSymbolAddress(&p, g_ew2h);  __half* pew2h  = (__half*)p;
    cudaGetSymbolAddress(&p, g_sw1h);  __half* psw1h  = (__half*)p;
    cudaGetSymbolAddress(&p, g_sw2h);  __half* psw2h  = (__half*)p;
    cudaGetSymbolAddress(&p, g_ffw1h); __half* pffw1h = (__half*)p;
    cudaGetSymbolAddress(&p, g_ffw2h); __half* pffw2h = (__half*)p;

    cudaFuncSetAttribute(mm_gemm<0, true,  true >, cudaFuncAttributeMaxDynamicSharedMemorySize, SMEM_TOTAL);
    cudaFuncSetAttribute(mm_gemm<2, false, true >, cudaFuncAttributeMaxDynamicSharedMemorySize, SMEM_TOTAL);
    cudaFuncSetAttribute(mm_gemm<0, false, false>, cudaFuncAttributeMaxDynamicSharedMemorySize, SMEM_TOTAL);
    cudaFuncSetAttribute(mm_gemm<1, false, false>, cudaFuncAttributeMaxDynamicSharedMemorySize, SMEM_TOTAL);
    cudaFuncSetAttribute(mm_gemm<3, false, false>, cudaFuncAttributeMaxDynamicSharedMemorySize, SMEM_TOTAL);

    // 1. fused weight conversion (one launch, 35840 blocks)
    cvt_all_kernel<<<35840, 256>>>(ew1, ew2, sw1, sw2, ffw1, ffw2,
                                   pew1h, pew2h, psw1h, psw2h, pffw1h, pffw2h);
    // 2. input LN + router top-2
    ln_kernel<0><<<TOKS, 128>>>(x, nullptr, ln_g, ln_b, rw, rb, ph);
    // 3. counts + offsets + tile map + scatter (one block)
    setup_scatter_kernel<<<1, 256>>>();
    // 4. expert GEMM1 + SiLU (gathered A rows) -> fp16
    mm_gemm<0, true, true><<<dim3(MAX_TILES, DHID/BN), 256, SMEM_TOTAL>>>(
        ph, pew1h, eb1, pact1, DMODEL, DHID, nullptr, nullptr, 1.0f);
    // 5. expert GEMM2 -> fp32 y
    mm_gemm<2, false, true><<<dim3(MAX_TILES, DMODEL/BN), 256, SMEM_TOTAL>>>(
        pact1, pew2h, eb2, py, DHID, DMODEL, nullptr, nullptr, 1.0f);
    // 6. shared expert GEMM1 + SiLU
    mm_gemm<0, false, false><<<dim3(TOKS/BM, DSH/BN), 256, SMEM_TOTAL>>>(
        ph, psw1h, sb1, psact, DMODEL, DSH, nullptr, nullptr, 1.0f);
    // 7. shared expert GEMM2 * 0.25 -> mix
    mm_gemm<1, false, false><<<dim3(TOKS/BM, DMODEL/BN), 256, SMEM_TOTAL>>>(
        psact, psw2h, sb2, pmix, DSH, DMODEL, nullptr, nullptr, SHARED_SCALE);
    // 8. combine(top-2) + final-FF LayerNorm -> fh (and updated mix)
    ln_kernel<1><<<TOKS, 128>>>(nullptr, pmix, ffln_g, ffln_b, nullptr, nullptr, pfh);
    // 9. FF GEMM1 + SiLU
    mm_gemm<0, false, false><<<dim3(TOKS/BM, DHID/BN), 256, SMEM_TOTAL>>>(
        pfh, pffw1h, ffb1, pffact, DMODEL, DHID, nullptr, nullptr, 1.0f);
    // 10. FF GEMM2 + x + moe_out -> out
    mm_gemm<3, false, false><<<dim3(TOKS/BM, DMODEL/BN), 256, SMEM_TOTAL>>>(
        pffact, pffw2h, ffb2, out, DHID, DMODEL, x, pmix, 1.0f);
}